// round 3
// baseline (speedup 1.0000x reference)
#include <cuda_runtime.h>
#include <math.h>

#define BATCH 32768
#define SEQ 50
#define D 16
#define XDIM 112
#define RPB 16   // rows per block in gather kernel (16 lanes per row * 16 rows = 256 thr)

// ---------------- scratch (no allocations allowed) ----------------
__device__ float g_x[BATCH * XDIM];   // raw features: [0:48) singles, [48:112) pooled (pre-BN)
__device__ float g_sum[64];
__device__ float g_sq[64];
__device__ float g_A[64];             // BN scale
__device__ float g_B[64];             // BN shift

// ---------------- f32x2 helpers (packed fp32 pair ops, 2x FFMA rate) ----------------
__device__ __forceinline__ unsigned long long ffma2(unsigned long long a,
                                                    unsigned long long b,
                                                    unsigned long long c) {
    unsigned long long d;
    asm("fma.rn.f32x2 %0, %1, %2, %3;" : "=l"(d) : "l"(a), "l"(b), "l"(c));
    return d;
}
__device__ __forceinline__ unsigned long long pack2(float lo, float hi) {
    unsigned long long d;
    asm("mov.b64 %0, {%1, %2};" : "=l"(d) : "f"(lo), "f"(hi));
    return d;
}
__device__ __forceinline__ void unpack2(unsigned long long v, float& lo, float& hi) {
    asm("mov.b64 {%0, %1}, %2;" : "=f"(lo), "=f"(hi) : "l"(v));
}

// ---------------- kernel 0: zero stats (graph replays!) ----------------
__global__ void k_zero() {
    int t = threadIdx.x;
    if (t < 64) { g_sum[t] = 0.f; g_sq[t] = 0.f; }
}

// ---------------- kernel 1: gathers + poolings + BN partial stats ----------------
__global__ void __launch_bounds__(256) k_gather(
    const int* __restrict__ user_id, const int* __restrict__ movie_id, const int* __restrict__ year,
    const int* __restrict__ ug, const int* __restrict__ urb,
    const int* __restrict__ mg, const int* __restrict__ mt,
    const int* __restrict__ ug_m, const int* __restrict__ urb_m,
    const int* __restrict__ mg_m, const int* __restrict__ mt_m,
    const float* __restrict__ Eu, const float* __restrict__ Em, const float* __restrict__ Et,
    const float* __restrict__ Eg, const float* __restrict__ Ey,
    const float* __restrict__ Am, const float* __restrict__ At, const float* __restrict__ Ag)
{
    __shared__ float s_sum[64], s_sq[64];
    int t = threadIdx.x;
    if (t < 64) { s_sum[t] = 0.f; s_sq[t] = 0.f; }
    __syncthreads();

    int r = blockIdx.x * RPB + (t >> 4);
    int lane = t & 15;
    unsigned gm = 0xFFFFu << (t & 16);   // shuffle mask for this 16-lane row group

    float* xrow = g_x + r * XDIM;

    // ---- single features ----
    xrow[lane]      = Eu[user_id[r]  * D + lane];
    xrow[16 + lane] = Em[movie_id[r] * D + lane];
    xrow[32 + lane] = Ey[year[r]     * D + lane];

    float p0, p1, p2, p3;

    // ---- f0: sum pooling over user_genre (genre table) ----
    {
        int cnt = ug_m[r];
        const int* ids = ug + r * SEQ;
        float acc = 0.f;
        for (int i = 0; i < cnt; i++) acc += Eg[ids[i] * D + lane];
        p0 = acc;
    }

    // ---- f1: attention pooling over urb (movie table) ----
    // softmax over all 50 positions where masked aw == 0 (exp(0)=1 per masked slot)
    {
        int cnt = urb_m[r];
        const int* ids = urb + r * SEQ;
        float num = 0.f, den = (float)(SEQ - cnt);
        for (int i = 0; i < cnt; i++) {
            int id = ids[i];
            float w = expf(Am[id]);
            num += Em[id * D + lane] * w;
            den += w;
        }
        p1 = num / den;
    }

    // ---- f2: max-L2 pooling over movie_genre (genre table) ----
    // argmax of per-position squared L2 norm; masked positions are zero (l2=0);
    // strict > preserves first-max tie-break; cnt==0 -> zeros.
    {
        int cnt = mg_m[r];
        const int* ids = mg + r * SEQ;
        float best = -1.f, bestE = 0.f;
        for (int i = 0; i < cnt; i++) {
            float e = Eg[ids[i] * D + lane];
            float l2 = __fmul_rn(e, e);
            l2 += __shfl_xor_sync(gm, l2, 8, 16);
            l2 += __shfl_xor_sync(gm, l2, 4, 16);
            l2 += __shfl_xor_sync(gm, l2, 2, 16);
            l2 += __shfl_xor_sync(gm, l2, 1, 16);
            if (l2 > best) { best = l2; bestE = e; }
        }
        p2 = bestE;
    }

    // ---- f3: korder pooling over movie_tag (tag table) ----
    // CRITICAL: s*s must be a separately-rounded multiply (no FMA contraction
    // with the -ss term). For cnt==1, s*s == ss bit-exactly in the reference,
    // so v must be exactly 0; a contracted FMA leaves a ~1e-9 rounding residue
    // that the v/||v|| normalization blows up into a garbage unit vector.
    {
        int cnt = mt_m[r];
        const int* ids = mt + r * SEQ;
        float s = 0.f, ss = 0.f;
        for (int i = 0; i < cnt; i++) {
            float e = Et[ids[i] * D + lane];
            s += e;
            ss = __fmaf_rn(e, e, ss);
        }
        float s2 = __fmul_rn(s, s);        // separately rounded, matches reference
        float v = 0.5f * __fadd_rn(s2, -ss);
        float n2 = __fmul_rn(v, v);
        n2 += __shfl_xor_sync(gm, n2, 8, 16);
        n2 += __shfl_xor_sync(gm, n2, 4, 16);
        n2 += __shfl_xor_sync(gm, n2, 2, 16);
        n2 += __shfl_xor_sync(gm, n2, 1, 16);
        float n = fmaxf(sqrtf(n2), 1e-12f);
        p3 = v / n;
    }

    // ---- write raw pooled features + BN partial stats ----
    xrow[48 + lane] = p0;
    xrow[64 + lane] = p1;
    xrow[80 + lane] = p2;
    xrow[96 + lane] = p3;

    atomicAdd(&s_sum[lane],      p0); atomicAdd(&s_sq[lane],      p0 * p0);
    atomicAdd(&s_sum[16 + lane], p1); atomicAdd(&s_sq[16 + lane], p1 * p1);
    atomicAdd(&s_sum[32 + lane], p2); atomicAdd(&s_sq[32 + lane], p2 * p2);
    atomicAdd(&s_sum[48 + lane], p3); atomicAdd(&s_sq[48 + lane], p3 * p3);
    __syncthreads();
    if (t < 64) {
        atomicAdd(&g_sum[t], s_sum[t]);
        atomicAdd(&g_sq[t],  s_sq[t]);
    }
}

// ---------------- kernel 2: finalize BN scale/shift ----------------
__global__ void k_bn(const float* __restrict__ gamma, const float* __restrict__ beta) {
    int t = threadIdx.x;   // 64 threads
    const float invB = 1.f / (float)BATCH;
    float mean = g_sum[t] * invB;
    float var  = g_sq[t] * invB - mean * mean;
    float a = gamma[t] * rsqrtf(var + 1e-5f);
    g_A[t] = a;
    g_B[t] = beta[t] - mean * a;
}

// ---------------- kernel 3: BN apply + MLP (f32x2 packed) ----------------
__global__ void __launch_bounds__(128) k_mlp(
    const float* __restrict__ W1, const float* __restrict__ b1,
    const float* __restrict__ W2, const float* __restrict__ b2,
    const float* __restrict__ W3, const float* __restrict__ b3,
    float* __restrict__ out)
{
    __shared__ __align__(16) float W1s[112 * 64];
    __shared__ __align__(16) float W2s[64 * 32];
    __shared__ float W3s[32];
    __shared__ float b1s[64], b2s[32];
    __shared__ float As[64], Bs[64];

    int t = threadIdx.x;
    for (int i = t; i < 112 * 64; i += 128) W1s[i] = W1[i];
    for (int i = t; i < 64 * 32; i += 128)  W2s[i] = W2[i];
    if (t < 32) W3s[t] = W3[t];
    if (t < 64) b1s[t] = b1[t];
    if (t < 32) b2s[t] = b2[t];
    if (t < 64) { As[t] = g_A[t]; Bs[t] = g_B[t]; }
    __syncthreads();

    int r = blockIdx.x * 128 + t;
    const float4* xr4 = (const float4*)(g_x + r * XDIM);

    // ---- layer 1: 112 -> 64, accumulate as 32 f32x2 pairs ----
    unsigned long long h[32];
    #pragma unroll
    for (int jp = 0; jp < 32; jp++) h[jp] = pack2(b1s[2 * jp], b1s[2 * jp + 1]);

    for (int kt = 0; kt < 14; kt++) {
        float4 a4 = xr4[2 * kt];
        float4 b4 = xr4[2 * kt + 1];
        float xr[8] = {a4.x, a4.y, a4.z, a4.w, b4.x, b4.y, b4.z, b4.w};
        int kbase = kt * 8;
        if (kbase >= 48) {   // BN applies only to the pooled section
            #pragma unroll
            for (int u = 0; u < 8; u++) {
                int c = kbase + u - 48;
                xr[u] = xr[u] * As[c] + Bs[c];
            }
        }
        #pragma unroll
        for (int u = 0; u < 8; u++) {
            unsigned long long xx = pack2(xr[u], xr[u]);
            const unsigned long long* wrow =
                (const unsigned long long*)(W1s + (kbase + u) * 64);
            #pragma unroll
            for (int jp = 0; jp < 32; jp++) h[jp] = ffma2(xx, wrow[jp], h[jp]);
        }
    }

    float h1[64];
    #pragma unroll
    for (int jp = 0; jp < 32; jp++) {
        float lo, hi; unpack2(h[jp], lo, hi);
        h1[2 * jp]     = fmaxf(lo, 0.f);
        h1[2 * jp + 1] = fmaxf(hi, 0.f);
    }

    // ---- layer 2: 64 -> 32 ----
    unsigned long long h2[16];
    #pragma unroll
    for (int jp = 0; jp < 16; jp++) h2[jp] = pack2(b2s[2 * jp], b2s[2 * jp + 1]);
    #pragma unroll 4
    for (int k = 0; k < 64; k++) {
        unsigned long long xx = pack2(h1[k], h1[k]);
        const unsigned long long* wrow = (const unsigned long long*)(W2s + k * 32);
        #pragma unroll
        for (int jp = 0; jp < 16; jp++) h2[jp] = ffma2(xx, wrow[jp], h2[jp]);
    }

    // ---- layer 3: 32 -> 1 + sigmoid ----
    float z = b3[0];
    #pragma unroll
    for (int jp = 0; jp < 16; jp++) {
        float lo, hi; unpack2(h2[jp], lo, hi);
        z += fmaxf(lo, 0.f) * W3s[2 * jp] + fmaxf(hi, 0.f) * W3s[2 * jp + 1];
    }
    out[r] = 1.f / (1.f + expf(-z));
}

// ---------------- launch ----------------
extern "C" void kernel_launch(void* const* d_in, const int* in_sizes, int n_in,
                              void* d_out, int out_size) {
    const int* user_id  = (const int*)d_in[0];
    const int* movie_id = (const int*)d_in[1];
    const int* year     = (const int*)d_in[2];
    const int* ug       = (const int*)d_in[3];
    const int* urb      = (const int*)d_in[4];
    const int* mg       = (const int*)d_in[5];
    const int* mt       = (const int*)d_in[6];
    const int* ug_m     = (const int*)d_in[7];
    const int* urb_m    = (const int*)d_in[8];
    const int* mg_m     = (const int*)d_in[9];
    const int* mt_m     = (const int*)d_in[10];
    const float* Eu     = (const float*)d_in[11];
    const float* Em     = (const float*)d_in[12];
    const float* Et     = (const float*)d_in[13];
    const float* Eg     = (const float*)d_in[14];
    const float* Ey     = (const float*)d_in[15];
    const float* Am     = (const float*)d_in[16];
    const float* At     = (const float*)d_in[17];
    const float* Ag     = (const float*)d_in[18];
    const float* gamma  = (const float*)d_in[19];
    const float* beta   = (const float*)d_in[20];
    const float* W1     = (const float*)d_in[21];
    const float* b1     = (const float*)d_in[22];
    const float* W2     = (const float*)d_in[23];
    const float* b2     = (const float*)d_in[24];
    const float* W3     = (const float*)d_in[25];
    const float* b3     = (const float*)d_in[26];

    k_zero<<<1, 64>>>();
    k_gather<<<BATCH / RPB, 256>>>(user_id, movie_id, year, ug, urb, mg, mt,
                                   ug_m, urb_m, mg_m, mt_m,
                                   Eu, Em, Et, Eg, Ey, Am, At, Ag);
    k_bn<<<1, 64>>>(gamma, beta);
    k_mlp<<<BATCH / 128, 128>>>(W1, b1, W2, b2, W3, b3, (float*)d_out);
}